// round 1
// baseline (speedup 1.0000x reference)
#include <cuda_runtime.h>
#include <cuda_bf16.h>

#define N_NODESC 100000
#define N_EDGESC 1600000
#define HID      128
#define H3       384
#define NCLS     10
#define NLAYERS  4
#define NGRAPHS  200
#define BN_EPSF  1e-5f

// ---------------- scratch (device globals; no allocation allowed) ----------
__device__ float d_h  [N_NODESC * HID];   // node state
__device__ float d_m  [N_NODESC * HID];   // per-layer message transform
__device__ float d_agg[N_NODESC * HID];   // scatter-add result
__device__ float d_gi [N_NODESC * H3];    // agg @ w_ih^T + b_ih
__device__ float d_gh [N_NODESC * H3];    // h   @ w_hh^T + b_hh
__device__ float d_y  [N_NODESC * HID];   // fc1 output
__device__ float d_wT [NLAYERS * HID * HID]; // transposed ggnn weights [l][j][k]
__device__ float d_bnacc[2 * HID];        // col sums / sumsq
__device__ float d_pool [NGRAPHS * HID];  // per-graph feature sums
__device__ float d_cnt  [NGRAPHS];        // per-graph node counts

// ---------------- utility kernels ------------------------------------------
__global__ void zero_kernel(float* __restrict__ p, int n) {
    int i = blockIdx.x * blockDim.x + threadIdx.x;
    if (i < n) p[i] = 0.f;
}

__global__ void copy_kernel(float* __restrict__ dst, const float* __restrict__ src, int n) {
    int i = blockIdx.x * blockDim.x + threadIdx.x;
    if (i < n) dst[i] = src[i];
}

// WT[l][j][k] = W[l][k][j]   (so m = h @ W becomes dot(h_row, WT_row_j))
__global__ void transpose_w_kernel(const float* __restrict__ W, float* __restrict__ WT) {
    int idx = blockIdx.x * blockDim.x + threadIdx.x;
    if (idx >= NLAYERS * HID * HID) return;
    int l = idx / (HID * HID);
    int j = (idx / HID) % HID;
    int k = idx % HID;
    WT[idx] = W[l * HID * HID + k * HID + j];
}

// ---------------- tiled SGEMM: C[N,M] = A[N,128] * B[M,128]^T (+bias) ------
// B stored row-major [M, K=128] (i.e. each output col = dot with B row).
// Block tile 64x64, 256 threads, 4x4 per thread, K chunked by 32.
__global__ __launch_bounds__(256) void sgemm_tn_kernel(
    const float* __restrict__ A, const float* __restrict__ B,
    const float* __restrict__ bias, float* __restrict__ C,
    int N, int M)
{
    const int K = 128;
    __shared__ float As[64][33];
    __shared__ float Bs[64][33];

    int tid  = threadIdx.x;
    int row0 = blockIdx.y * 64;
    int col0 = blockIdx.x * 64;
    int tx = tid & 15;       // 0..15 -> output cols
    int ty = tid >> 4;       // 0..15 -> output rows

    float acc[4][4] = {};

    for (int k0 = 0; k0 < K; k0 += 32) {
#pragma unroll
        for (int i = 0; i < 8; i++) {
            int idx = tid + i * 256;        // 0..2047
            int r = idx >> 5;               // 0..63
            int c = idx & 31;               // 0..31
            int gr = row0 + r;
            As[r][c] = (gr < N) ? A[(size_t)gr * K + k0 + c] : 0.f;
            Bs[r][c] = B[(size_t)(col0 + r) * K + k0 + c];   // M multiple of 64
        }
        __syncthreads();
#pragma unroll
        for (int kk = 0; kk < 32; kk++) {
            float a[4], b[4];
#pragma unroll
            for (int i = 0; i < 4; i++) a[i] = As[ty * 4 + i][kk];
#pragma unroll
            for (int j = 0; j < 4; j++) b[j] = Bs[tx * 4 + j][kk];
#pragma unroll
            for (int i = 0; i < 4; i++)
#pragma unroll
                for (int j = 0; j < 4; j++) acc[i][j] += a[i] * b[j];
        }
        __syncthreads();
    }

#pragma unroll
    for (int i = 0; i < 4; i++) {
        int gr = row0 + ty * 4 + i;
        if (gr >= N) continue;
#pragma unroll
        for (int j = 0; j < 4; j++) {
            int gc = col0 + tx * 4 + j;
            float v = acc[i][j];
            if (bias) v += bias[gc];
            C[(size_t)gr * M + gc] = v;
        }
    }
}

// ---------------- edge scatter-add: agg[dst] += m[src] ----------------------
// One warp per edge; each lane handles a float4 (128 floats / edge).
__global__ void scatter_add_kernel(const float* __restrict__ m,
                                   const int* __restrict__ src,
                                   const int* __restrict__ dst,
                                   float* __restrict__ agg)
{
    int e = (blockIdx.x * blockDim.x + threadIdx.x) >> 5;
    if (e >= N_EDGESC) return;
    int lane = threadIdx.x & 31;
    int s = src[e], d = dst[e];
    float4 v = reinterpret_cast<const float4*>(m + (size_t)s * HID)[lane];
    float* a = agg + (size_t)d * HID + lane * 4;
    atomicAdd(a + 0, v.x);
    atomicAdd(a + 1, v.y);
    atomicAdd(a + 2, v.z);
    atomicAdd(a + 3, v.w);
}

// ---------------- GRU gate fuse --------------------------------------------
__global__ void gru_gate_kernel(float* __restrict__ h,
                                const float* __restrict__ gi,
                                const float* __restrict__ gh)
{
    int idx = blockIdx.x * blockDim.x + threadIdx.x;
    if (idx >= N_NODESC * HID) return;
    int n = idx / HID, j = idx % HID;
    const float* gin = gi + (size_t)n * H3;
    const float* ghn = gh + (size_t)n * H3;
    float ir = gin[j], iz = gin[HID + j], inn = gin[2 * HID + j];
    float hr = ghn[j], hz = ghn[HID + j], hn  = ghn[2 * HID + j];
    float r = 1.f / (1.f + __expf(-(ir + hr)));
    float z = 1.f / (1.f + __expf(-(iz + hz)));
    float nn = tanhf(inn + r * hn);
    float hv = h[idx];
    h[idx] = (1.f - z) * nn + z * hv;
}

// ---------------- batchnorm column stats -----------------------------------
__global__ void bn_stats_kernel(const float* __restrict__ y, float* __restrict__ acc)
{
    int j = threadIdx.x;  // 128 threads = 128 columns
    float s = 0.f, s2 = 0.f;
    for (int row = blockIdx.x; row < N_NODESC; row += gridDim.x) {
        float v = y[(size_t)row * HID + j];
        s += v; s2 += v * v;
    }
    atomicAdd(&acc[j], s);
    atomicAdd(&acc[HID + j], s2);
}

// ---------------- normalize + relu + per-graph sum pool --------------------
// batch is sorted; accumulate runs per graph, flush on transition.
__global__ void norm_pool_kernel(const float* __restrict__ y,
                                 const int* __restrict__ batch,
                                 const float* __restrict__ acc,
                                 const float* __restrict__ gamma,
                                 const float* __restrict__ beta,
                                 float* __restrict__ pool)
{
    int j = threadIdx.x;  // 128
    float mean = acc[j] * (1.f / N_NODESC);
    float var  = acc[HID + j] * (1.f / N_NODESC) - mean * mean;
    float sc = rsqrtf(var + BN_EPSF) * gamma[j];
    float sh = beta[j] - mean * sc;

    int r0 = blockIdx.x * 256;
    int r1 = min(r0 + 256, N_NODESC);
    float av = 0.f;
    int gcur = -1;
    for (int row = r0; row < r1; row++) {
        int g = batch[row];
        float v = y[(size_t)row * HID + j] * sc + sh;
        v = fmaxf(v, 0.f);
        if (g != gcur) {
            if (gcur >= 0) atomicAdd(&pool[gcur * HID + j], av);
            av = 0.f; gcur = g;
        }
        av += v;
    }
    if (gcur >= 0) atomicAdd(&pool[gcur * HID + j], av);
}

__global__ void count_kernel(const int* __restrict__ batch, float* __restrict__ cnt)
{
    int n = blockIdx.x * blockDim.x + threadIdx.x;
    if (n < N_NODESC) atomicAdd(&cnt[batch[n]], 1.0f);
}

// ---------------- head: mean pool -> fc2 -> log_softmax --------------------
__global__ void head_kernel(const float* __restrict__ pool,
                            const float* __restrict__ cnt,
                            const float* __restrict__ w2,
                            const float* __restrict__ b2,
                            float* __restrict__ out)
{
    int g = blockIdx.x;        // 200 graphs
    int lane = threadIdx.x;    // 32
    float invc = 1.f / fmaxf(cnt[g], 1.f);
    float f[4];
#pragma unroll
    for (int i = 0; i < 4; i++) f[i] = pool[g * HID + lane * 4 + i] * invc;

    __shared__ float logits[NCLS];
    for (int c = 0; c < NCLS; c++) {
        float p = 0.f;
#pragma unroll
        for (int i = 0; i < 4; i++) p += f[i] * w2[c * HID + lane * 4 + i];
#pragma unroll
        for (int o = 16; o; o >>= 1) p += __shfl_xor_sync(0xffffffffu, p, o);
        if (lane == 0) logits[c] = p + b2[c];
    }
    __syncwarp();
    if (lane == 0) {
        float mx = -1e30f;
        for (int c = 0; c < NCLS; c++) mx = fmaxf(mx, logits[c]);
        float se = 0.f;
        for (int c = 0; c < NCLS; c++) se += expf(logits[c] - mx);
        float lse = mx + logf(se);
        for (int c = 0; c < NCLS; c++) out[g * NCLS + c] = logits[c] - lse;
    }
}

// ---------------- launch ----------------------------------------------------
extern "C" void kernel_launch(void* const* d_in, const int* in_sizes, int n_in,
                              void* d_out, int out_size)
{
    const float* x      = (const float*)d_in[0];
    const int*   ei     = (const int*)  d_in[1];   // [2, E] int32 (jax x64 off)
    const int*   batch  = (const int*)  d_in[2];
    const float* ggnn_w = (const float*)d_in[3];
    const float* w_ih   = (const float*)d_in[4];
    const float* w_hh   = (const float*)d_in[5];
    const float* b_ih   = (const float*)d_in[6];
    const float* b_hh   = (const float*)d_in[7];
    const float* fc1_w  = (const float*)d_in[8];
    const float* fc1_b  = (const float*)d_in[9];
    const float* gamma  = (const float*)d_in[10];
    const float* beta   = (const float*)d_in[11];
    const float* fc2_w  = (const float*)d_in[12];
    const float* fc2_b  = (const float*)d_in[13];
    float* out = (float*)d_out;

    float *h_, *m_, *agg_, *gi_, *gh_, *y_, *wT_, *bn_, *pool_, *cnt_;
    cudaGetSymbolAddress((void**)&h_,    d_h);
    cudaGetSymbolAddress((void**)&m_,    d_m);
    cudaGetSymbolAddress((void**)&agg_,  d_agg);
    cudaGetSymbolAddress((void**)&gi_,   d_gi);
    cudaGetSymbolAddress((void**)&gh_,   d_gh);
    cudaGetSymbolAddress((void**)&y_,    d_y);
    cudaGetSymbolAddress((void**)&wT_,   d_wT);
    cudaGetSymbolAddress((void**)&bn_,   d_bnacc);
    cudaGetSymbolAddress((void**)&pool_, d_pool);
    cudaGetSymbolAddress((void**)&cnt_,  d_cnt);

    const int NH = N_NODESC * HID;          // 12.8M
    const dim3 g_rows((unsigned)( (N_NODESC + 63) / 64 ));  // 1563

    // init: h = x ; transpose ggnn weights
    copy_kernel<<<(NH + 255) / 256, 256>>>(h_, x, NH);
    transpose_w_kernel<<<(NLAYERS * HID * HID + 255) / 256, 256>>>(ggnn_w, wT_);

    for (int l = 0; l < NLAYERS; l++) {
        // m = h @ W_l
        sgemm_tn_kernel<<<dim3(HID / 64, g_rows.x), 256>>>(
            h_, wT_ + (size_t)l * HID * HID, nullptr, m_, N_NODESC, HID);
        // agg = segment_sum(m[src], dst)
        zero_kernel<<<(NH + 255) / 256, 256>>>(agg_, NH);
        scatter_add_kernel<<<(N_EDGESC * 32 + 255) / 256, 256>>>(
            m_, ei, ei + N_EDGESC, agg_);
        // gi = agg @ w_ih^T + b_ih ; gh = h @ w_hh^T + b_hh
        sgemm_tn_kernel<<<dim3(H3 / 64, g_rows.x), 256>>>(
            agg_, w_ih, b_ih, gi_, N_NODESC, H3);
        sgemm_tn_kernel<<<dim3(H3 / 64, g_rows.x), 256>>>(
            h_, w_hh, b_hh, gh_, N_NODESC, H3);
        // h = GRU(agg, h)
        gru_gate_kernel<<<(NH + 255) / 256, 256>>>(h_, gi_, gh_);
    }

    // y = h @ fc1_w^T + fc1_b
    sgemm_tn_kernel<<<dim3(HID / 64, g_rows.x), 256>>>(
        h_, fc1_w, fc1_b, y_, N_NODESC, HID);

    // batchnorm stats + normalize/relu + pooled sums
    zero_kernel<<<1, 256>>>(bn_, 2 * HID);
    zero_kernel<<<(NGRAPHS * HID + 255) / 256, 256>>>(pool_, NGRAPHS * HID);
    zero_kernel<<<1, 256>>>(cnt_, NGRAPHS);
    bn_stats_kernel<<<512, 128>>>(y_, bn_);
    count_kernel<<<(N_NODESC + 255) / 256, 256>>>(batch, cnt_);
    norm_pool_kernel<<<(N_NODESC + 255) / 256, 128>>>(
        y_, batch, bn_, gamma, beta, pool_);

    // head
    head_kernel<<<NGRAPHS, 32>>>(pool_, cnt_, fc2_w, fc2_b, out);
}

// round 3
// speedup vs baseline: 1.9926x; 1.9926x over previous
#include <cuda_runtime.h>
#include <cuda_bf16.h>
#include <cstdint>

#define N_NODESC 100000
#define N_EDGESC 1600000
#define HID      128
#define H3       384
#define NCLS     10
#define NLAYERS  4
#define NGRAPHS  200
#define BN_EPSF  1e-5f

// ---------------- scratch (device globals; no allocation allowed) ----------
__device__ float d_h   [N_NODESC * HID];
__device__ float d_m   [N_NODESC * HID];
__device__ float d_agg [N_NODESC * HID];
__device__ float d_gi  [N_NODESC * H3];
__device__ float d_gh  [N_NODESC * H3];
__device__ float d_y   [N_NODESC * HID];
__device__ float d_bcat[NLAYERS * 512 * HID];  // per-layer [W_l^T ; w_hh] packed, rows=out col
__device__ float d_bnacc[2 * HID];
__device__ float d_pool [NGRAPHS * HID];
__device__ float d_cnt  [NGRAPHS];

// ---------------- helpers ---------------------------------------------------
__device__ __forceinline__ unsigned f2tf32(float f) {
    unsigned u;
    asm("cvt.rna.tf32.f32 %0, %1;" : "=r"(u) : "f"(f));
    return u;
}

__device__ __forceinline__ void mma_tf32(float c[4], const unsigned a[4], const unsigned b[2]) {
    asm volatile(
        "mma.sync.aligned.m16n8k8.row.col.f32.tf32.tf32.f32 "
        "{%0,%1,%2,%3}, {%4,%5,%6,%7}, {%8,%9}, {%0,%1,%2,%3};"
        : "+f"(c[0]), "+f"(c[1]), "+f"(c[2]), "+f"(c[3])
        : "r"(a[0]), "r"(a[1]), "r"(a[2]), "r"(a[3]), "r"(b[0]), "r"(b[1]));
}

// ---------------- pack B_cat: rows 0..127 = W_l^T, rows 128..511 = w_hh -----
__global__ void pack_bcat_kernel(const float* __restrict__ W,
                                 const float* __restrict__ w_hh,
                                 float* __restrict__ bcat)
{
    int idx = blockIdx.x * blockDim.x + threadIdx.x;
    if (idx >= NLAYERS * 512 * HID) return;
    int l = idx / (512 * HID);
    int j = (idx / HID) % 512;
    int k = idx % HID;
    float v;
    if (j < HID) v = W[l * HID * HID + k * HID + j];   // (h@W)[j] = sum_k h[k] W[k][j]
    else         v = w_hh[(j - HID) * HID + k];
    bcat[idx] = v;
}

// ---------------- tf32 tensor-core GEMM: C[N,M] = A[N,128] * B[M,128]^T ----
// Block 64x64, 128 threads (2x2 warps, warp tile 32x32 via m16n8k8).
// Column-split epilogue: cols < split -> out0 (+bias0), cols >= split -> out1 (+bias1).
#define SMEM_STRIDE 132
__global__ __launch_bounds__(128) void gemm_tf32_kernel(
    const float* __restrict__ A, const float* __restrict__ B, int N,
    float* __restrict__ out0, int ld0, const float* __restrict__ bias0,
    int split, float* __restrict__ out1, int ld1, const float* __restrict__ bias1)
{
    extern __shared__ unsigned smem_u[];
    unsigned* As = smem_u;                      // 64 x 132
    unsigned* Bs = smem_u + 64 * SMEM_STRIDE;   // 64 x 132

    const int tid  = threadIdx.x;
    const int row0 = blockIdx.y * 64;
    const int col0 = blockIdx.x * 64;

    // load + convert A,B tiles (full K=128)
#pragma unroll
    for (int i = 0; i < 16; i++) {
        int idx = tid + i * 128;            // 0..2047
        int r   = idx >> 5;                 // 0..63
        int c4  = idx & 31;                 // float4 index 0..31
        int gr  = row0 + r;
        float4 va = (gr < N) ? *reinterpret_cast<const float4*>(A + (size_t)gr * HID + c4 * 4)
                             : make_float4(0.f, 0.f, 0.f, 0.f);
        float4 vb = *reinterpret_cast<const float4*>(B + (size_t)(col0 + r) * HID + c4 * 4);
        uint4 ua = make_uint4(f2tf32(va.x), f2tf32(va.y), f2tf32(va.z), f2tf32(va.w));
        uint4 ub = make_uint4(f2tf32(vb.x), f2tf32(vb.y), f2tf32(vb.z), f2tf32(vb.w));
        *reinterpret_cast<uint4*>(&As[r * SMEM_STRIDE + c4 * 4]) = ua;
        *reinterpret_cast<uint4*>(&Bs[r * SMEM_STRIDE + c4 * 4]) = ub;
    }
    __syncthreads();

    const int warp = tid >> 5;
    const int lane = tid & 31;
    const int wr = warp >> 1;    // 0..1 row of warp grid
    const int wc = warp & 1;     // 0..1 col
    const int gid = lane >> 2;   // 0..7
    const int tig = lane & 3;    // 0..3

    float acc[2][4][4] = {};

#pragma unroll
    for (int ks = 0; ks < 16; ks++) {
        const int k0 = ks * 8;
        unsigned af[2][4];
#pragma unroll
        for (int mt = 0; mt < 2; mt++) {
            int rb = wr * 32 + mt * 16;
            af[mt][0] = As[(rb + gid    ) * SMEM_STRIDE + k0 + tig];
            af[mt][1] = As[(rb + gid + 8) * SMEM_STRIDE + k0 + tig];
            af[mt][2] = As[(rb + gid    ) * SMEM_STRIDE + k0 + tig + 4];
            af[mt][3] = As[(rb + gid + 8) * SMEM_STRIDE + k0 + tig + 4];
        }
        unsigned bf[4][2];
#pragma unroll
        for (int nt = 0; nt < 4; nt++) {
            int cb = wc * 32 + nt * 8;
            bf[nt][0] = Bs[(cb + gid) * SMEM_STRIDE + k0 + tig];
            bf[nt][1] = Bs[(cb + gid) * SMEM_STRIDE + k0 + tig + 4];
        }
#pragma unroll
        for (int mt = 0; mt < 2; mt++)
#pragma unroll
            for (int nt = 0; nt < 4; nt++)
                mma_tf32(acc[mt][nt], af[mt], bf[nt]);
    }

    // epilogue with optional column split
#pragma unroll
    for (int mt = 0; mt < 2; mt++) {
#pragma unroll
        for (int hh = 0; hh < 2; hh++) {
            int gr = row0 + wr * 32 + mt * 16 + gid + hh * 8;
            if (gr >= N) continue;
#pragma unroll
            for (int nt = 0; nt < 4; nt++) {
#pragma unroll
                for (int cc = 0; cc < 2; cc++) {
                    int gc = col0 + wc * 32 + nt * 8 + tig * 2 + cc;
                    float v = acc[mt][nt][hh * 2 + cc];
                    if (gc < split) {
                        if (bias0) v += bias0[gc];
                        out0[(size_t)gr * ld0 + gc] = v;
                    } else {
                        int c1 = gc - split;
                        if (bias1) v += bias1[c1];
                        out1[(size_t)gr * ld1 + c1] = v;
                    }
                }
            }
        }
    }
}

// ---------------- edge scatter-add: agg[dst] += m[src] (vector red) ---------
__global__ void scatter_add_kernel(const float* __restrict__ m,
                                   const int* __restrict__ src,
                                   const int* __restrict__ dst,
                                   float* __restrict__ agg)
{
    int e = (blockIdx.x * blockDim.x + threadIdx.x) >> 5;
    if (e >= N_EDGESC) return;
    int lane = threadIdx.x & 31;
    int s = src[e], d = dst[e];
    float4 v = reinterpret_cast<const float4*>(m + (size_t)s * HID)[lane];
    float* a = agg + (size_t)d * HID + lane * 4;
    asm volatile("red.global.add.v4.f32 [%0], {%1, %2, %3, %4};"
                 :: "l"(a), "f"(v.x), "f"(v.y), "f"(v.z), "f"(v.w) : "memory");
}

// ---------------- GRU gate fuse (float4) ------------------------------------
__global__ void gru_gate_kernel(float* __restrict__ h,
                                const float* __restrict__ gi,
                                const float* __restrict__ gh)
{
    int idx = blockIdx.x * blockDim.x + threadIdx.x;
    if (idx >= N_NODESC * 32) return;
    int n = idx >> 5, q = idx & 31;
    const float4* gi4 = reinterpret_cast<const float4*>(gi + (size_t)n * H3);
    const float4* gh4 = reinterpret_cast<const float4*>(gh + (size_t)n * H3);
    float4* h4 = reinterpret_cast<float4*>(h + (size_t)n * HID);
    float4 ir = gi4[q], iz = gi4[32 + q], in_ = gi4[64 + q];
    float4 hr = gh4[q], hz = gh4[32 + q], hn  = gh4[64 + q];
    float4 hv = h4[q];
    float4 o;
    {
        float r = 1.f / (1.f + __expf(-(ir.x + hr.x)));
        float z = 1.f / (1.f + __expf(-(iz.x + hz.x)));
        float nn = tanhf(in_.x + r * hn.x);
        o.x = (1.f - z) * nn + z * hv.x;
    }
    {
        float r = 1.f / (1.f + __expf(-(ir.y + hr.y)));
        float z = 1.f / (1.f + __expf(-(iz.y + hz.y)));
        float nn = tanhf(in_.y + r * hn.y);
        o.y = (1.f - z) * nn + z * hv.y;
    }
    {
        float r = 1.f / (1.f + __expf(-(ir.z + hr.z)));
        float z = 1.f / (1.f + __expf(-(iz.z + hz.z)));
        float nn = tanhf(in_.z + r * hn.z);
        o.z = (1.f - z) * nn + z * hv.z;
    }
    {
        float r = 1.f / (1.f + __expf(-(ir.w + hr.w)));
        float z = 1.f / (1.f + __expf(-(iz.w + hz.w)));
        float nn = tanhf(in_.w + r * hn.w);
        o.w = (1.f - z) * nn + z * hv.w;
    }
    h4[q] = o;
}

// ---------------- batchnorm column stats -----------------------------------
__global__ void bn_stats_kernel(const float* __restrict__ y, float* __restrict__ acc)
{
    int j = threadIdx.x;  // 128 columns
    float s = 0.f, s2 = 0.f;
    for (int row = blockIdx.x; row < N_NODESC; row += gridDim.x) {
        float v = y[(size_t)row * HID + j];
        s += v; s2 += v * v;
    }
    atomicAdd(&acc[j], s);
    atomicAdd(&acc[HID + j], s2);
}

// ---------------- normalize + relu + per-graph sum pool --------------------
__global__ void norm_pool_kernel(const float* __restrict__ y,
                                 const int* __restrict__ batch,
                                 const float* __restrict__ acc,
                                 const float* __restrict__ gamma,
                                 const float* __restrict__ beta,
                                 float* __restrict__ pool)
{
    int j = threadIdx.x;  // 128
    float mean = acc[j] * (1.f / N_NODESC);
    float var  = acc[HID + j] * (1.f / N_NODESC) - mean * mean;
    float sc = rsqrtf(var + BN_EPSF) * gamma[j];
    float sh = beta[j] - mean * sc;

    int r0 = blockIdx.x * 256;
    int r1 = min(r0 + 256, N_NODESC);
    float av = 0.f;
    int gcur = -1;
    for (int row = r0; row < r1; row++) {
        int g = batch[row];
        float v = y[(size_t)row * HID + j] * sc + sh;
        v = fmaxf(v, 0.f);
        if (g != gcur) {
            if (gcur >= 0) atomicAdd(&pool[gcur * HID + j], av);
            av = 0.f; gcur = g;
        }
        av += v;
    }
    if (gcur >= 0) atomicAdd(&pool[gcur * HID + j], av);
}

__global__ void count_kernel(const int* __restrict__ batch, float* __restrict__ cnt)
{
    int n = blockIdx.x * blockDim.x + threadIdx.x;
    if (n < N_NODESC) atomicAdd(&cnt[batch[n]], 1.0f);
}

// ---------------- head: mean pool -> fc2 -> log_softmax --------------------
__global__ void head_kernel(const float* __restrict__ pool,
                            const float* __restrict__ cnt,
                            const float* __restrict__ w2,
                            const float* __restrict__ b2,
                            float* __restrict__ out)
{
    int g = blockIdx.x;
    int lane = threadIdx.x;    // 32
    float invc = 1.f / fmaxf(cnt[g], 1.f);
    float f[4];
#pragma unroll
    for (int i = 0; i < 4; i++) f[i] = pool[g * HID + lane * 4 + i] * invc;

    __shared__ float logits[NCLS];
    for (int c = 0; c < NCLS; c++) {
        float p = 0.f;
#pragma unroll
        for (int i = 0; i < 4; i++) p += f[i] * w2[c * HID + lane * 4 + i];
#pragma unroll
        for (int o = 16; o; o >>= 1) p += __shfl_xor_sync(0xffffffffu, p, o);
        if (lane == 0) logits[c] = p + b2[c];
    }
    __syncwarp();
    if (lane == 0) {
        float mx = -1e30f;
        for (int c = 0; c < NCLS; c++) mx = fmaxf(mx, logits[c]);
        float se = 0.f;
        for (int c = 0; c < NCLS; c++) se += expf(logits[c] - mx);
        float lse = mx + logf(se);
        for (int c = 0; c < NCLS; c++) out[g * NCLS + c] = logits[c] - lse;
    }
}

// ---------------- launch ----------------------------------------------------
extern "C" void kernel_launch(void* const* d_in, const int* in_sizes, int n_in,
                              void* d_out, int out_size)
{
    const float* x      = (const float*)d_in[0];
    const int*   ei     = (const int*)  d_in[1];   // [2, E] int32
    const int*   batch  = (const int*)  d_in[2];
    const float* ggnn_w = (const float*)d_in[3];
    const float* w_ih   = (const float*)d_in[4];
    const float* w_hh   = (const float*)d_in[5];
    const float* b_ih   = (const float*)d_in[6];
    const float* b_hh   = (const float*)d_in[7];
    const float* fc1_w  = (const float*)d_in[8];
    const float* fc1_b  = (const float*)d_in[9];
    const float* gamma  = (const float*)d_in[10];
    const float* beta   = (const float*)d_in[11];
    const float* fc2_w  = (const float*)d_in[12];
    const float* fc2_b  = (const float*)d_in[13];
    float* out = (float*)d_out;

    float *h_, *m_, *agg_, *gi_, *gh_, *y_, *bcat_, *bn_, *pool_, *cnt_;
    cudaGetSymbolAddress((void**)&h_,    d_h);
    cudaGetSymbolAddress((void**)&m_,    d_m);
    cudaGetSymbolAddress((void**)&agg_,  d_agg);
    cudaGetSymbolAddress((void**)&gi_,   d_gi);
    cudaGetSymbolAddress((void**)&gh_,   d_gh);
    cudaGetSymbolAddress((void**)&y_,    d_y);
    cudaGetSymbolAddress((void**)&bcat_, d_bcat);
    cudaGetSymbolAddress((void**)&bn_,   d_bnacc);
    cudaGetSymbolAddress((void**)&pool_, d_pool);
    cudaGetSymbolAddress((void**)&cnt_,  d_cnt);

    const int NH = N_NODESC * HID;
    const unsigned ROWB = (N_NODESC + 63) / 64;    // 1563
    const size_t smem_bytes = 2u * 64u * SMEM_STRIDE * 4u;  // 67584

    cudaFuncSetAttribute(gemm_tf32_kernel,
                         cudaFuncAttributeMaxDynamicSharedMemorySize, (int)smem_bytes);

    // init: h = x ; pack fused B matrices
    cudaMemcpyAsync(h_, x, (size_t)NH * 4, cudaMemcpyDeviceToDevice);
    pack_bcat_kernel<<<(NLAYERS * 512 * HID + 255) / 256, 256>>>(ggnn_w, w_hh, bcat_);

    for (int l = 0; l < NLAYERS; l++) {
        // fused: [m | gh] = h @ [W_l^T ; w_hh]^T   (cols<128 -> m, else gh + b_hh)
        gemm_tf32_kernel<<<dim3(512 / 64, ROWB), 128, smem_bytes>>>(
            h_, bcat_ + (size_t)l * 512 * HID, N_NODESC,
            m_, HID, nullptr, HID, gh_, H3, b_hh);
        // agg = segment_sum(m[src], dst)
        cudaMemsetAsync(agg_, 0, (size_t)NH * 4);
        scatter_add_kernel<<<(N_EDGESC * 32 + 255) / 256, 256>>>(
            m_, ei, ei + N_EDGESC, agg_);
        // gi = agg @ w_ih^T + b_ih
        gemm_tf32_kernel<<<dim3(H3 / 64, ROWB), 128, smem_bytes>>>(
            agg_, w_ih, N_NODESC,
            gi_, H3, b_ih, H3 + 1, nullptr, 0, nullptr);
        // h = GRU(agg, h)
        gru_gate_kernel<<<(N_NODESC * 32 + 255) / 256, 256>>>(h_, gi_, gh_);
    }

    // y = h @ fc1_w^T + fc1_b
    gemm_tf32_kernel<<<dim3(HID / 64, ROWB), 128, smem_bytes>>>(
        h_, fc1_w, N_NODESC,
        y_, HID, fc1_b, HID + 1, nullptr, 0, nullptr);

    // batchnorm stats + normalize/relu + pooled sums
    cudaMemsetAsync(bn_, 0, 2 * HID * 4);
    cudaMemsetAsync(pool_, 0, NGRAPHS * HID * 4);
    cudaMemsetAsync(cnt_, 0, NGRAPHS * 4);
    bn_stats_kernel<<<512, 128>>>(y_, bn_);
    count_kernel<<<(N_NODESC + 255) / 256, 256>>>(batch, cnt_);
    norm_pool_kernel<<<(N_NODESC + 255) / 256, 128>>>(
        y_, batch, bn_, gamma, beta, pool_);

    // head
    head_kernel<<<NGRAPHS, 32>>>(pool_, cnt_, fc2_w, fc2_b, out);
}

// round 6
// speedup vs baseline: 2.2184x; 1.1133x over previous
#include <cuda_runtime.h>
#include <cuda_bf16.h>
#include <cstdint>

#define N_NODESC 100000
#define N_EDGESC 1600000
#define HID      128
#define H3       384
#define NCLS     10
#define NLAYERS  4
#define NGRAPHS  200
#define BN_EPSF  1e-5f

// ---------------- scratch (device globals; no allocation allowed) ----------
__device__ float d_h   [N_NODESC * HID];
__device__ float d_m   [N_NODESC * HID];
__device__ float d_agg [N_NODESC * HID];
__device__ float d_gi  [N_NODESC * H3];
__device__ float d_gh  [N_NODESC * H3];
__device__ float d_y   [N_NODESC * HID];
// bf16 B images, row pitch 136 bf16 (272B): 2048 rows fused layers, 384 w_ih, 128 fc1
__device__ __align__(1024) __nv_bfloat16 d_bimg[2560 * 136];
__device__ float d_bnacc[2 * HID];
__device__ float d_pool [NGRAPHS * HID];
__device__ float d_cnt  [NGRAPHS];

// ---------------- helpers ---------------------------------------------------
__device__ __forceinline__ uint32_t smem_u32(const void* p) {
    return (uint32_t)__cvta_generic_to_shared(p);
}

__device__ __forceinline__ void ldmx4(uint32_t r[4], uint32_t addr) {
    asm volatile("ldmatrix.sync.aligned.m8n8.x4.shared.b16 {%0,%1,%2,%3}, [%4];"
                 : "=r"(r[0]), "=r"(r[1]), "=r"(r[2]), "=r"(r[3]) : "r"(addr));
}

__device__ __forceinline__ void mma_bf16(float c[4], const uint32_t a[4], const uint32_t b[2]) {
    asm volatile(
        "mma.sync.aligned.m16n8k16.row.col.f32.bf16.bf16.f32 "
        "{%0,%1,%2,%3}, {%4,%5,%6,%7}, {%8,%9}, {%0,%1,%2,%3};"
        : "+f"(c[0]), "+f"(c[1]), "+f"(c[2]), "+f"(c[3])
        : "r"(a[0]), "r"(a[1]), "r"(a[2]), "r"(a[3]), "r"(b[0]), "r"(b[1]));
}

// ---------------- pack B weights -> bf16 image, pitch 136 -------------------
// rows 0..2047: layer l = r>>9, rr=r&511: rr<128 -> W_l^T row rr, else w_hh row rr-128
// rows 2048..2431: w_ih ; rows 2432..2559: fc1_w
__global__ void pack_b_kernel(const float* __restrict__ W,
                              const float* __restrict__ w_hh,
                              const float* __restrict__ w_ih,
                              const float* __restrict__ fc1_w,
                              __nv_bfloat16* __restrict__ bimg)
{
    int idx = blockIdx.x * blockDim.x + threadIdx.x;
    if (idx >= 2560 * 128) return;
    int r = idx >> 7;
    int k = idx & 127;
    float v;
    if (r < 2048) {
        int l = r >> 9, rr = r & 511;
        v = (rr < HID) ? W[l * HID * HID + k * HID + rr]   // (h@W)[j]: row j = W[:,j]
                       : w_hh[(rr - HID) * HID + k];
    } else if (r < 2432) {
        v = w_ih[(r - 2048) * HID + k];
    } else {
        v = fc1_w[(r - 2432) * HID + k];
    }
    bimg[r * 136 + k] = __float2bfloat16(v);
}

// ---------------- bf16 tensor-core GEMM: C = A[N,128] * B^T ------------------
// CTA tile: 128 rows x 128 cols, 256 threads = 8 warps (4 m x 2 n), warp 32x64.
// A fp32->bf16 converted into smem (pitch 272B); B tile copied from image.
// ldmatrix.x4 fragment loads; mma.m16n8k16 bf16.
// Split epilogue on global col: < split -> out0 (+bias0) else out1 (+bias1).
#define PITCHB 272
#define SMB_OFF 34816
__global__ __launch_bounds__(256) void gemm_bf16_kernel(
    const float* __restrict__ A, const __nv_bfloat16* __restrict__ Bimg,
    int nrows,
    float* __restrict__ out0, int ld0, const float* __restrict__ bias0,
    int split, float* __restrict__ out1, int ld1, const float* __restrict__ bias1)
{
    extern __shared__ char smem[];
    const int tid    = threadIdx.x;
    const int row0   = blockIdx.y * 128;
    const int colblk = blockIdx.x;

    // A: fp32 -> bf16 into smem, 128 rows x 128 cols, pitch 272B
    for (int i = tid; i < 128 * 32; i += 256) {
        int r = i >> 5, c4 = i & 31;
        int gr = row0 + r;
        float4 v = (gr < nrows)
            ? *reinterpret_cast<const float4*>(A + (size_t)gr * HID + c4 * 4)
            : make_float4(0.f, 0.f, 0.f, 0.f);
        __nv_bfloat162 lo = __float22bfloat162_rn(make_float2(v.x, v.y));
        __nv_bfloat162 hi = __float22bfloat162_rn(make_float2(v.z, v.w));
        uint2 pk;
        pk.x = *reinterpret_cast<uint32_t*>(&lo);
        pk.y = *reinterpret_cast<uint32_t*>(&hi);
        *reinterpret_cast<uint2*>(smem + r * PITCHB + c4 * 8) = pk;
    }
    // B: copy 128 rows x 272B from image (row-block colblk), already bf16
    {
        const uint4* src = reinterpret_cast<const uint4*>(
            reinterpret_cast<const char*>(Bimg) + (size_t)colblk * 128 * PITCHB);
        uint4* dst = reinterpret_cast<uint4*>(smem + SMB_OFF);
        for (int i = tid; i < 128 * PITCHB / 16; i += 256) dst[i] = src[i];
    }
    __syncthreads();

    const int wid  = tid >> 5;
    const int lane = tid & 31;
    const int wm = wid & 3;      // 4 row-warps, 32 rows each
    const int wn = wid >> 2;     // 2 col-warps, 64 cols each
    const uint32_t sa  = smem_u32(smem);
    const uint32_t sbB = sa + SMB_OFF;

    float acc[2][8][4] = {};

    // ldmatrix lane address components
    const int a_row  = wm * 32 + (lane & 15);
    const int a_koff = (lane >> 4) * 16;                       // k-half byte offset
    const int b_row  = wn * 64 + ((lane >> 4) & 1) * 8 + (lane & 7);
    const int b_koff = ((lane >> 3) & 1) * 16;

#pragma unroll
    for (int ks = 0; ks < 8; ks++) {
        const int kb = ks * 32;    // 16 bf16 = 32B per kstep
        uint32_t af[2][4];
#pragma unroll
        for (int mt = 0; mt < 2; mt++)
            ldmx4(af[mt], sa + (uint32_t)((a_row + mt * 16) * PITCHB + kb + a_koff));
        uint32_t bf[8][2];
#pragma unroll
        for (int p = 0; p < 4; p++) {
            uint32_t r4[4];
            ldmx4(r4, sbB + (uint32_t)((b_row + p * 16) * PITCHB + kb + b_koff));
            bf[2 * p][0] = r4[0]; bf[2 * p][1] = r4[1];
            bf[2 * p + 1][0] = r4[2]; bf[2 * p + 1][1] = r4[3];
        }
#pragma unroll
        for (int mt = 0; mt < 2; mt++)
#pragma unroll
            for (int nt = 0; nt < 8; nt++)
                mma_bf16(acc[mt][nt], af[mt], bf[nt]);
    }

    // epilogue
    const int gid = lane >> 2, t4 = lane & 3;
#pragma unroll
    for (int mt = 0; mt < 2; mt++) {
#pragma unroll
        for (int hh = 0; hh < 2; hh++) {
            int gr = row0 + wm * 32 + mt * 16 + gid + hh * 8;
            if (gr >= nrows) continue;
#pragma unroll
            for (int nt = 0; nt < 8; nt++) {
                int gc = colblk * 128 + wn * 64 + nt * 8 + t4 * 2;
                float vx = acc[mt][nt][hh * 2 + 0];
                float vy = acc[mt][nt][hh * 2 + 1];
                if (gc < split) {
                    if (bias0) { vx += bias0[gc]; vy += bias0[gc + 1]; }
                    *reinterpret_cast<float2*>(out0 + (size_t)gr * ld0 + gc) =
                        make_float2(vx, vy);
                } else {
                    int c1 = gc - split;
                    if (bias1) { vx += bias1[c1]; vy += bias1[c1 + 1]; }
                    *reinterpret_cast<float2*>(out1 + (size_t)gr * ld1 + c1) =
                        make_float2(vx, vy);
                }
            }
        }
    }
}

// ---------------- edge scatter-add: agg[dst] += m[src] (vector red) ---------
__global__ void scatter_add_kernel(const float* __restrict__ m,
                                   const int* __restrict__ src,
                                   const int* __restrict__ dst,
                                   float* __restrict__ agg)
{
    int e = (blockIdx.x * blockDim.x + threadIdx.x) >> 5;
    if (e >= N_EDGESC) return;
    int lane = threadIdx.x & 31;
    int s = src[e], d = dst[e];
    float4 v = reinterpret_cast<const float4*>(m + (size_t)s * HID)[lane];
    float* a = agg + (size_t)d * HID + lane * 4;
    asm volatile("red.global.add.v4.f32 [%0], {%1, %2, %3, %4};"
                 :: "l"(a), "f"(v.x), "f"(v.y), "f"(v.z), "f"(v.w) : "memory");
}

// ---------------- GRU gate fuse (float4) ------------------------------------
__global__ void gru_gate_kernel(float* __restrict__ h,
                                const float* __restrict__ gi,
                                const float* __restrict__ gh)
{
    int idx = blockIdx.x * blockDim.x + threadIdx.x;
    if (idx >= N_NODESC * 32) return;
    int n = idx >> 5, q = idx & 31;
    const float4* gi4 = reinterpret_cast<const float4*>(gi + (size_t)n * H3);
    const float4* gh4 = reinterpret_cast<const float4*>(gh + (size_t)n * H3);
    float4* h4 = reinterpret_cast<float4*>(h + (size_t)n * HID);
    float4 ir = gi4[q], iz = gi4[32 + q], in_ = gi4[64 + q];
    float4 hr = gh4[q], hz = gh4[32 + q], hn  = gh4[64 + q];
    float4 hv = h4[q];
    float4 o;
    { float r = 1.f/(1.f+__expf(-(ir.x+hr.x))); float z = 1.f/(1.f+__expf(-(iz.x+hz.x)));
      float nn = tanhf(in_.x + r*hn.x); o.x = (1.f-z)*nn + z*hv.x; }
    { float r = 1.f/(1.f+__expf(-(ir.y+hr.y))); float z = 1.f/(1.f+__expf(-(iz.y+hz.y)));
      float nn = tanhf(in_.y + r*hn.y); o.y = (1.f-z)*nn + z*hv.y; }
    { float r = 1.f/(1.f+__expf(-(ir.z+hr.z))); float z = 1.f/(1.f+__expf(-(iz.z+hz.z)));
      float nn = tanhf(in_.z + r*hn.z); o.z = (1.f-z)*nn + z*hv.z; }
    { float r = 1.f/(1.f+__expf(-(ir.w+hr.w))); float z = 1.f/(1.f+__expf(-(iz.w+hz.w)));
      float nn = tanhf(in_.w + r*hn.w); o.w = (1.f-z)*nn + z*hv.w; }
    h4[q] = o;
}

// ---------------- batchnorm column stats -----------------------------------
__global__ void bn_stats_kernel(const float* __restrict__ y, float* __restrict__ acc)
{
    int j = threadIdx.x;
    float s = 0.f, s2 = 0.f;
    for (int row = blockIdx.x; row < N_NODESC; row += gridDim.x) {
        float v = y[(size_t)row * HID + j];
        s += v; s2 += v * v;
    }
    atomicAdd(&acc[j], s);
    atomicAdd(&acc[HID + j], s2);
}

// ---------------- normalize + relu + per-graph sum pool --------------------
__global__ void norm_pool_kernel(const float* __restrict__ y,
                                 const int* __restrict__ batch,
                                 const float* __restrict__ acc,
                                 const float* __restrict__ gamma,
                                 const float* __restrict__ beta,
                                 float* __restrict__ pool)
{
    int j = threadIdx.x;
    float mean = acc[j] * (1.f / N_NODESC);
    float var  = acc[HID + j] * (1.f / N_NODESC) - mean * mean;
    float sc = rsqrtf(var + BN_EPSF) * gamma[j];
    float sh = beta[j] - mean * sc;

    int r0 = blockIdx.x * 256;
    int r1 = min(r0 + 256, N_NODESC);
    float av = 0.f;
    int gcur = -1;
    for (int row = r0; row < r1; row++) {
        int g = batch[row];
        float v = y[(size_t)row * HID + j] * sc + sh;
        v = fmaxf(v, 0.f);
        if (g != gcur) {
            if (gcur >= 0) atomicAdd(&pool[gcur * HID + j], av);
            av = 0.f; gcur = g;
        }
        av += v;
    }
    if (gcur >= 0) atomicAdd(&pool[gcur * HID + j], av);
}

__global__ void count_kernel(const int* __restrict__ batch, float* __restrict__ cnt)
{
    int n = blockIdx.x * blockDim.x + threadIdx.x;
    if (n < N_NODESC) atomicAdd(&cnt[batch[n]], 1.0f);
}

// ---------------- head: mean pool -> fc2 -> log_softmax --------------------
__global__ void head_kernel(const float* __restrict__ pool,
                            const float* __restrict__ cnt,
                            const float* __restrict__ w2,
                            const float* __restrict__ b2,
                            float* __restrict__ out)
{
    int g = blockIdx.x;
    int lane = threadIdx.x;
    float invc = 1.f / fmaxf(cnt[g], 1.f);
    float f[4];
#pragma unroll
    for (int i = 0; i < 4; i++) f[i] = pool[g * HID + lane * 4 + i] * invc;

    __shared__ float logits[NCLS];
    for (int c = 0; c < NCLS; c++) {
        float p = 0.f;
#pragma unroll
        for (int i = 0; i < 4; i++) p += f[i] * w2[c * HID + lane * 4 + i];
#pragma unroll
        for (int o = 16; o; o >>= 1) p += __shfl_xor_sync(0xffffffffu, p, o);
        if (lane == 0) logits[c] = p + b2[c];
    }
    __syncwarp();
    if (lane == 0) {
        float mx = -1e30f;
        for (int c = 0; c < NCLS; c++) mx = fmaxf(mx, logits[c]);
        float se = 0.f;
        for (int c = 0; c < NCLS; c++) se += expf(logits[c] - mx);
        float lse = mx + logf(se);
        for (int c = 0; c < NCLS; c++) out[g * NCLS + c] = logits[c] - lse;
    }
}

// ---------------- launch ----------------------------------------------------
extern "C" void kernel_launch(void* const* d_in, const int* in_sizes, int n_in,
                              void* d_out, int out_size)
{
    const float* x      = (const float*)d_in[0];
    const int*   ei     = (const int*)  d_in[1];   // [2, E] int32
    const int*   batch  = (const int*)  d_in[2];
    const float* ggnn_w = (const float*)d_in[3];
    const float* w_ih   = (const float*)d_in[4];
    const float* w_hh   = (const float*)d_in[5];
    const float* b_ih   = (const float*)d_in[6];
    const float* b_hh   = (const float*)d_in[7];
    const float* fc1_w  = (const float*)d_in[8];
    const float* fc1_b  = (const float*)d_in[9];
    const float* gamma  = (const float*)d_in[10];
    const float* beta   = (const float*)d_in[11];
    const float* fc2_w  = (const float*)d_in[12];
    const float* fc2_b  = (const float*)d_in[13];
    float* out = (float*)d_out;

    float *h_, *m_, *agg_, *gi_, *gh_, *y_, *bn_, *pool_, *cnt_;
    __nv_bfloat16* bimg_;
    cudaGetSymbolAddress((void**)&h_,    d_h);
    cudaGetSymbolAddress((void**)&m_,    d_m);
    cudaGetSymbolAddress((void**)&agg_,  d_agg);
    cudaGetSymbolAddress((void**)&gi_,   d_gi);
    cudaGetSymbolAddress((void**)&gh_,   d_gh);
    cudaGetSymbolAddress((void**)&y_,    d_y);
    cudaGetSymbolAddress((void**)&bimg_, d_bimg);
    cudaGetSymbolAddress((void**)&bn_,   d_bnacc);
    cudaGetSymbolAddress((void**)&pool_, d_pool);
    cudaGetSymbolAddress((void**)&cnt_,  d_cnt);

    const int NH = N_NODESC * HID;
    const unsigned ROWB = (N_NODESC + 127) / 128;   // 782
    const int smem_bytes = 2 * 34816;               // 69632
    cudaFuncSetAttribute(gemm_bf16_kernel,
                         cudaFuncAttributeMaxDynamicSharedMemorySize, smem_bytes);

    // init: h = x ; pack bf16 B images
    cudaMemcpyAsync(h_, x, (size_t)NH * 4, cudaMemcpyDeviceToDevice);
    pack_b_kernel<<<(2560 * 128 + 255) / 256, 256>>>(ggnn_w, w_hh, w_ih, fc1_w, bimg_);

    for (int l = 0; l < NLAYERS; l++) {
        // fused: [m | gh] = h @ [W_l^T ; w_hh]^T  (global col < 128 -> m, else gh + b_hh)
        gemm_bf16_kernel<<<dim3(4, ROWB), 256, smem_bytes>>>(
            h_, bimg_ + (size_t)l * 512 * 136, N_NODESC,
            m_, HID, nullptr, HID, gh_, H3, b_hh);
        // agg = segment_sum(m[src], dst)
        cudaMemsetAsync(agg_, 0, (size_t)NH * 4);
        scatter_add_kernel<<<(N_EDGESC * 32 + 255) / 256, 256>>>(
            m_, ei, ei + N_EDGESC, agg_);
        // gi = agg @ w_ih^T + b_ih
        gemm_bf16_kernel<<<dim3(3, ROWB), 256, smem_bytes>>>(
            agg_, bimg_ + 2048 * 136, N_NODESC,
            gi_, H3, b_ih, 1 << 30, nullptr, 0, nullptr);
        // h = GRU(agg, h)
        gru_gate_kernel<<<(N_NODESC * 32 + 255) / 256, 256>>>(h_, gi_, gh_);
    }

    // y = h @ fc1_w^T + fc1_b
    gemm_bf16_kernel<<<dim3(1, ROWB), 256, smem_bytes>>>(
        h_, bimg_ + 2432 * 136, N_NODESC,
        y_, HID, fc1_b, 1 << 30, nullptr, 0, nullptr);

    // batchnorm stats + normalize/relu + pooled sums
    cudaMemsetAsync(bn_, 0, 2 * HID * 4);
    cudaMemsetAsync(pool_, 0, NGRAPHS * HID * 4);
    cudaMemsetAsync(cnt_, 0, NGRAPHS * 4);
    bn_stats_kernel<<<512, 128>>>(y_, bn_);
    count_kernel<<<(N_NODESC + 255) / 256, 256>>>(batch, cnt_);
    norm_pool_kernel<<<(N_NODESC + 255) / 256, 128>>>(
        y_, batch, bn_, gamma, beta, pool_);

    // head
    head_kernel<<<NGRAPHS, 32>>>(pool_, cnt_, fc2_w, fc2_b, out);
}